// round 16
// baseline (speedup 1.0000x reference)
#include <cuda_runtime.h>
#include <cuda_bf16.h>
#include <math.h>
#include <stdint.h>

#define SQ   2048
#define D    1024
#define NH   16
#define DK   64
#define DFF  4096

// ================= PTX helpers (baseline ISA, sm_80-level) ===================
__device__ __forceinline__ uint32_t smem_u32(const void* p) {
    uint32_t a;
    asm("{ .reg .u64 t; cvta.to.shared.u64 t, %1; cvt.u32.u64 %0, t; }" : "=r"(a) : "l"(p));
    return a;
}
__device__ __forceinline__ void cpa16(uint32_t dst, const void* src) {
    asm volatile("cp.async.cg.shared.global [%0], [%1], 16;" :: "r"(dst), "l"(src));
}
#define CPA_COMMIT() asm volatile("cp.async.commit_group;" ::: "memory")
__device__ __forceinline__ void ldm_x4(uint32_t& r0, uint32_t& r1, uint32_t& r2, uint32_t& r3, uint32_t addr) {
    asm volatile("ldmatrix.sync.aligned.m8n8.x4.shared.b16 {%0,%1,%2,%3}, [%4];"
                 : "=r"(r0), "=r"(r1), "=r"(r2), "=r"(r3) : "r"(addr));
}
__device__ __forceinline__ void ldm_x2(uint32_t& r0, uint32_t& r1, uint32_t addr) {
    asm volatile("ldmatrix.sync.aligned.m8n8.x2.shared.b16 {%0,%1}, [%2];"
                 : "=r"(r0), "=r"(r1) : "r"(addr));
}
__device__ __forceinline__ uint32_t f2tf(uint32_t x) {
    uint32_t r;
    asm("cvt.rna.tf32.f32 %0, %1;" : "=r"(r) : "f"(__uint_as_float(x)));
    return r;
}
__device__ __forceinline__ float f2tff(float x) {
    uint32_t r;
    asm("cvt.rna.tf32.f32 %0, %1;" : "=r"(r) : "f"(x));
    return __uint_as_float(r);
}
__device__ __forceinline__ void mma_tf32(float* c, uint32_t a0, uint32_t a1, uint32_t a2, uint32_t a3,
                                         uint32_t b0, uint32_t b1) {
    asm volatile("mma.sync.aligned.m16n8k8.row.col.f32.tf32.tf32.f32 "
                 "{%0,%1,%2,%3}, {%4,%5,%6,%7}, {%8,%9}, {%0,%1,%2,%3};"
                 : "+f"(c[0]), "+f"(c[1]), "+f"(c[2]), "+f"(c[3])
                 : "r"(a0), "r"(a1), "r"(a2), "r"(a3), "r"(b0), "r"(b1));
}
__device__ __forceinline__ float wred_max(float v) {
#pragma unroll
    for (int o = 16; o > 0; o >>= 1) v = fmaxf(v, __shfl_xor_sync(0xffffffffu, v, o));
    return v;
}
__device__ __forceinline__ float wred_sum(float v) {
#pragma unroll
    for (int o = 16; o > 0; o >>= 1) v += __shfl_xor_sync(0xffffffffu, v, o);
    return v;
}

// ================= scratch ====================================================
__device__ float g_nx[SQ * D];
__device__ float g_h[SQ * D];
__device__ float g_qkv[SQ * 3 * D];
__device__ float g_ctx[SQ * D];
__device__ float g_mha[SQ * D];
__device__ float g_p1[SQ * D];
__device__ float g_n2[SQ * D];
__device__ float g_n2t[SQ * D];
__device__ float g_ff1[SQ * DFF];
__device__ float g_attn_scratch[(size_t)NH * SQ * SQ];
__device__ float g_wint[D * D];
__device__ float g_wqkvt[3 * D * D];
__device__ float g_wot[D * D];
__device__ float g_w2t[D * D];
__device__ float g_wf1t[DFF * D];
__device__ float g_wf2t[D * DFF];
__device__ float g_bqkv[3 * D];

// ================= weight prep: transpose + tf32 truncate ====================
__device__ __forceinline__ void wprep_tile(
    const float* __restrict__ W, float* __restrict__ T,
    int K, int N, int rowoff, int n0, int k0)
{
    __shared__ float t[32][33];
    const int tx = threadIdx.x, ty = threadIdx.y;
    for (int i = ty; i < 32; i += 8)
        t[i][tx] = W[(size_t)(k0 + i) * N + n0 + tx];
    __syncthreads();
    for (int i = ty; i < 32; i += 8)
        T[(size_t)(rowoff + n0 + i) * K + k0 + tx] = f2tff(t[tx][i]);
}

__global__ __launch_bounds__(256) void wprep_dd(
    const float* __restrict__ W_in, const float* __restrict__ Wq,
    const float* __restrict__ Wk,   const float* __restrict__ Wv,
    const float* __restrict__ Wo,   const float* __restrict__ W2,
    const float* __restrict__ bq,   const float* __restrict__ bk,
    const float* __restrict__ bv,
    float* wint, float* wqkvt, float* wot, float* w2t, float* bqkv)
{
    const int z = blockIdx.z;
    const float* W; float* T; int rowoff = 0;
    switch (z) {
        case 0:  W = W_in; T = wint;  break;
        case 1:  W = Wq;   T = wqkvt; rowoff = 0;     break;
        case 2:  W = Wk;   T = wqkvt; rowoff = D;     break;
        case 3:  W = Wv;   T = wqkvt; rowoff = 2 * D; break;
        case 4:  W = Wo;   T = wot;   break;
        default: W = W2;   T = w2t;   break;
    }
    wprep_tile(W, T, D, D, rowoff, blockIdx.x * 32, blockIdx.y * 32);
    if (z >= 1 && z <= 3 && blockIdx.x == 0 && blockIdx.y == 0) {
        const float* b = (z == 1) ? bq : (z == 2) ? bk : bv;
        for (int j = threadIdx.y * 32 + threadIdx.x; j < D; j += 256)
            bqkv[(z - 1) * D + j] = b[j];
    }
}

__global__ __launch_bounds__(256) void wprep_ff(
    const float* __restrict__ Wf1, const float* __restrict__ Wf2,
    float* f1t, float* f2t)
{
    if (blockIdx.z == 0)
        wprep_tile(Wf1, f1t, D, DFF, 0, blockIdx.x * 32, blockIdx.y * 32);
    else
        wprep_tile(Wf2, f2t, DFF, D, 0, blockIdx.y * 32, blockIdx.x * 32);
}

// ================= LayerNorm =================================================
template<int DUAL>
__global__ __launch_bounds__(256) void ln_kernel(
    const float* __restrict__ x, const float* __restrict__ g,
    const float* __restrict__ b, float* __restrict__ outf, float* __restrict__ outt)
{
    __shared__ float red[8];
    __shared__ float bc[2];
    const int row = blockIdx.x;
    const int tid = threadIdx.x;
    const int lane = tid & 31, warp = tid >> 5;
    float4 v = *(const float4*)(x + (size_t)row * D + tid * 4);

    float s = wred_sum(v.x + v.y + v.z + v.w);
    if (lane == 0) red[warp] = s;
    __syncthreads();
    if (warp == 0) {
        float t = red[lane & 7];
        t += __shfl_xor_sync(0xffffffffu, t, 1);
        t += __shfl_xor_sync(0xffffffffu, t, 2);
        t += __shfl_xor_sync(0xffffffffu, t, 4);
        if (lane == 0) bc[0] = t;
    }
    __syncthreads();
    const float mean = bc[0] * (1.0f / D);
    const float dx = v.x - mean, dy = v.y - mean, dz = v.z - mean, dw = v.w - mean;

    float s2 = wred_sum(dx * dx + dy * dy + dz * dz + dw * dw);
    if (lane == 0) red[warp] = s2;
    __syncthreads();
    if (warp == 0) {
        float t = red[lane & 7];
        t += __shfl_xor_sync(0xffffffffu, t, 1);
        t += __shfl_xor_sync(0xffffffffu, t, 2);
        t += __shfl_xor_sync(0xffffffffu, t, 4);
        if (lane == 0) bc[1] = t;
    }
    __syncthreads();
    const float inv = 1.0f / (sqrtf(bc[1] * (1.0f / D)) + 1e-6f);

    float4 gg = *(const float4*)(g + tid * 4);
    float4 bb = *(const float4*)(b + tid * 4);
    float o0 = gg.x * dx * inv + bb.x;
    float o1 = gg.y * dy * inv + bb.y;
    float o2 = gg.z * dz * inv + bb.z;
    float o3 = gg.w * dw * inv + bb.w;
    const size_t base = (size_t)row * D + tid * 4;
    if (DUAL) {
        float4 o4 = {o0, o1, o2, o3};
        *(float4*)(outf + base) = o4;
    }
    float4 t4v = {f2tff(o0), f2tff(o1), f2tff(o2), f2tff(o3)};
    *(float4*)(outt + base) = t4v;
}

// ================= shared GEMM plumbing (fp32 tiles, 128B rows) ==============
__device__ __forceinline__ uint32_t swzf(int row, int g) {
    return (uint32_t)(row * 128 + ((g ^ (row & 7)) << 4));
}

template<int ROWS, int THREADS>
__device__ __forceinline__ void load_tf(
    const float* __restrict__ gp, int ld, int row0, int k0, uint32_t sbase, int tid)
{
#pragma unroll
    for (int it = 0; it < ROWS * 8 / THREADS; it++) {
        int c = tid + it * THREADS;
        int row = c >> 3, g = c & 7;
        cpa16(sbase + swzf(row, g), gp + (size_t)(row0 + row) * ld + k0 + g * 4);
    }
}

// ================= TF32 GEMM: C = A[M,K] @ T[N,K]^T ==========================
// BN==128: 256 thr, occ 2, warp tile 32x64 (MT=2, NT=8)
// BN==64 : 128 thr, occ 4, warp tile 64x32 (MT=4, NT=4)
template<int BN, int RELU, int RESID, int CVT>
__global__ __launch_bounds__((BN == 128) ? 256 : 128, (BN == 128) ? 2 : 4) void tf_gemm(
    const float* __restrict__ A, const float* __restrict__ B,
    const float* __restrict__ bias, const float* __restrict__ res,
    float* __restrict__ C, int N, int K)
{
    constexpr int THREADS = (BN == 128) ? 256 : 128;
    constexpr int MT  = (BN == 128) ? 2 : 4;
    constexpr int NT  = (BN == 128) ? 8 : 4;
    constexpr int SA  = 0;
    constexpr int SB  = 16384;
    constexpr int SSZ = 16384 + BN * 128;

    extern __shared__ char smem[];
    const uint32_t sb = smem_u32(smem);
    const int tid = threadIdx.x, wid = tid >> 5, lane = tid & 31;
    const int warp_m = (BN == 128) ? (wid & 3) : (wid & 1);
    const int warp_n = (BN == 128) ? (wid >> 2) : (wid >> 1);
    const int brow = blockIdx.y * 128, bcol = blockIdx.x * BN;

    float acc[MT][NT][4];
#pragma unroll
    for (int a = 0; a < MT; a++)
#pragma unroll
        for (int b = 0; b < NT; b++)
#pragma unroll
            for (int c = 0; c < 4; c++) acc[a][b][c] = 0.0f;

    const int nch = K >> 5;
    load_tf<128, THREADS>(A, K, brow, 0, sb + SA, tid);
    load_tf<BN, THREADS>(B, K, bcol, 0, sb + SB, tid);
    CPA_COMMIT();

    const int tileA = lane >> 3;
    const int rinA  = (lane & 7) + ((tileA & 1) << 3);
    const int gA    = tileA >> 1;
    const int i16   = lane & 15;
    const int rinB  = i16 & 7;
    const int gB    = i16 >> 3;

    for (int i = 0; i < nch; i++) {
        if (i + 1 < nch) {
            const uint32_t st = sb + ((i + 1) & 1) * SSZ;
            const int k0 = (i + 1) << 5;
            load_tf<128, THREADS>(A, K, brow, k0, st + SA, tid);
            load_tf<BN, THREADS>(B, K, bcol, k0, st + SB, tid);
            CPA_COMMIT();
            asm volatile("cp.async.wait_group 1;" ::: "memory");
        } else {
            asm volatile("cp.async.wait_group 0;" ::: "memory");
        }
        __syncthreads();

        const uint32_t st = sb + (i & 1) * SSZ;
#pragma unroll
        for (int ks = 0; ks < 4; ks++) {
            uint32_t b0[NT], b1[NT];
#pragma unroll
            for (int nt = 0; nt < NT; nt++) {
                const int rowb = warp_n * (NT * 8) + nt * 8 + rinB;
                ldm_x2(b0[nt], b1[nt], st + SB + swzf(rowb, 2 * ks + gB));
            }
#pragma unroll
            for (int mt = 0; mt < MT; mt++) {
                const int rowa = warp_m * (MT * 16) + mt * 16 + rinA;
                uint32_t a0, a1, a2, a3;
                ldm_x4(a0, a1, a2, a3, st + SA + swzf(rowa, 2 * ks + gA));
#pragma unroll
                for (int nt = 0; nt < NT; nt++)
                    mma_tf32(acc[mt][nt], a0, a1, a2, a3, b0[nt], b1[nt]);
            }
        }
        __syncthreads();
    }

    const int g4 = lane >> 2, t4 = lane & 3;
#pragma unroll
    for (int mt = 0; mt < MT; mt++) {
#pragma unroll
        for (int half = 0; half < 2; half++) {
            const int row = brow + warp_m * (MT * 16) + mt * 16 + g4 + half * 8;
#pragma unroll
            for (int nt = 0; nt < NT; nt++) {
                const int col = bcol + warp_n * (NT * 8) + nt * 8 + t4 * 2;
                float v0 = acc[mt][nt][half * 2 + 0] + bias[col];
                float v1 = acc[mt][nt][half * 2 + 1] + bias[col + 1];
                if (RELU) { v0 = fmaxf(v0, 0.0f); v1 = fmaxf(v1, 0.0f); }
                const size_t o = (size_t)row * N + col;
                if (RESID) { v0 += res[o]; v1 += res[o + 1]; }
                if (CVT) { v0 = f2tff(v0); v1 = f2tff(v1); }
                float2 f2 = {v0, v1};
                *(float2*)(C + o) = f2;
            }
        }
    }
}

#define GSMEM_128 (2 * (16384 + 16384))
#define GSMEM_64  (2 * (16384 + 8192))

// ================= score (TF32): S = (Q K^T)/8, causal =======================
// 256 thr, warp tile 32x64 (MT=2, NT=8)
#define SC_SSZ (16384 + 16384)
#define SCORE_SMEM (2 * SC_SSZ)

__global__ __launch_bounds__(256, 2) void score_mma(
    const float* __restrict__ q, const float* __restrict__ k,
    float* __restrict__ attn)
{
    const int brow = blockIdx.y * 128, bcol = blockIdx.x * 128;
    if (bcol >= brow + 128) return;
    const int h = blockIdx.z;
    const float* A = q + h * DK;
    const float* B = k + h * DK;

    extern __shared__ char smem[];
    const uint32_t sb = smem_u32(smem);
    const int tid = threadIdx.x, wid = tid >> 5, lane = tid & 31;
    const int warp_m = wid & 3, warp_n = wid >> 2;

    float acc[2][8][4];
#pragma unroll
    for (int a = 0; a < 2; a++)
#pragma unroll
        for (int b = 0; b < 8; b++)
#pragma unroll
            for (int c = 0; c < 4; c++) acc[a][b][c] = 0.0f;

    load_tf<128, 256>(A, 3 * D, brow, 0, sb, tid);
    load_tf<128, 256>(B, 3 * D, bcol, 0, sb + 16384, tid);
    CPA_COMMIT();

    const int tileA = lane >> 3;
    const int rinA  = (lane & 7) + ((tileA & 1) << 3);
    const int gA    = tileA >> 1;
    const int i16   = lane & 15;
    const int rinB  = i16 & 7;
    const int gB    = i16 >> 3;

    for (int i = 0; i < 2; i++) {
        if (i == 0) {
            const uint32_t st = sb + SC_SSZ;
            load_tf<128, 256>(A, 3 * D, brow, 32, st, tid);
            load_tf<128, 256>(B, 3 * D, bcol, 32, st + 16384, tid);
            CPA_COMMIT();
            asm volatile("cp.async.wait_group 1;" ::: "memory");
        } else {
            asm volatile("cp.async.wait_group 0;" ::: "memory");
        }
        __syncthreads();

        const uint32_t st = sb + (i & 1) * SC_SSZ;
#pragma unroll
        for (int ks = 0; ks < 4; ks++) {
            uint32_t b0[8], b1[8];
#pragma unroll
            for (int nt = 0; nt < 8; nt++) {
                const int rowb = warp_n * 64 + nt * 8 + rinB;
                ldm_x2(b0[nt], b1[nt], st + 16384 + swzf(rowb, 2 * ks + gB));
            }
#pragma unroll
            for (int mt = 0; mt < 2; mt++) {
                const int rowa = warp_m * 32 + mt * 16 + rinA;
                uint32_t a0, a1, a2, a3;
                ldm_x4(a0, a1, a2, a3, st + swzf(rowa, 2 * ks + gA));
#pragma unroll
                for (int nt = 0; nt < 8; nt++)
                    mma_tf32(acc[mt][nt], a0, a1, a2, a3, b0[nt], b1[nt]);
            }
        }
        __syncthreads();
    }

    const int g4 = lane >> 2, t4 = lane & 3;
#pragma unroll
    for (int mt = 0; mt < 2; mt++) {
#pragma unroll
        for (int half = 0; half < 2; half++) {
            const int row = brow + warp_m * 32 + mt * 16 + g4 + half * 8;
            float* arow = attn + ((size_t)h * SQ + row) * SQ;
#pragma unroll
            for (int nt = 0; nt < 8; nt++) {
                const int col = bcol + warp_n * 64 + nt * 8 + t4 * 2;
                if (col <= row)     arow[col]     = acc[mt][nt][half * 2 + 0] * 0.125f;
                if (col + 1 <= row) arow[col + 1] = acc[mt][nt][half * 2 + 1] * 0.125f;
            }
        }
    }
}

// ================= softmax (fp32, vectorized fills) ==========================
__global__ __launch_bounds__(256) void softmax_kernel(float* __restrict__ attn)
{
    __shared__ float p[SQ];
    __shared__ float red[8];
    __shared__ float bc[2];
    const int i   = blockIdx.x;
    const int h   = blockIdx.y;
    const int tid = threadIdx.x;
    const int lane = tid & 31, warp = tid >> 5;
    float* row = attn + ((size_t)h * SQ + i) * SQ;

    float m = -INFINITY;
    for (int j = tid; j <= i; j += 256) { float s = row[j]; p[j] = s; m = fmaxf(m, s); }
    m = wred_max(m);
    if (lane == 0) red[warp] = m;
    __syncthreads();
    if (warp == 0) {
        float t = red[lane & 7];
        t = fmaxf(t, __shfl_xor_sync(0xffffffffu, t, 1));
        t = fmaxf(t, __shfl_xor_sync(0xffffffffu, t, 2));
        t = fmaxf(t, __shfl_xor_sync(0xffffffffu, t, 4));
        if (lane == 0) bc[0] = t;
    }
    __syncthreads();
    const float mx = bc[0];

    float sum = 0.0f;
    for (int j = tid; j <= i; j += 256) { float e = __expf(p[j] - mx); p[j] = e; sum += e; }
    sum = wred_sum(sum);
    __syncthreads();
    if (lane == 0) red[warp] = sum;
    __syncthreads();
    if (warp == 0) {
        float t = red[lane & 7];
        t += __shfl_xor_sync(0xffffffffu, t, 1);
        t += __shfl_xor_sync(0xffffffffu, t, 2);
        t += __shfl_xor_sync(0xffffffffu, t, 4);
        if (lane == 0) bc[1] = t;
    }
    __syncthreads();
    const float inv = 1.0f / bc[1];

    for (int j = tid; j <= i; j += 256) row[j] = p[j] * inv;

    const int zs = i + 1;
    const int za = (zs + 3) & ~3;
    if (tid < za - zs && zs + tid < SQ) row[zs + tid] = 0.0f;
    const float4 zf4 = {0.0f, 0.0f, 0.0f, 0.0f};
    for (int j = za + tid * 4; j < SQ; j += 1024) *(float4*)(row + j) = zf4;
}

// ================= AV (TF32): ctx = P @ V (unchanged) ========================
#define AV_A   0
#define AV_B   16384
#define AV_SSZ (16384 + 32 * 72 * 4)
#define AV_SMEM (2 * AV_SSZ)

__global__ __launch_bounds__(256, 2) void av_mma(
    const float* __restrict__ attn, const float* __restrict__ v,
    float* __restrict__ ctx)
{
    const int brow = blockIdx.x * 128;
    const int h    = blockIdx.y;
    const float* A = attn + (size_t)h * SQ * SQ;
    const float* V = v + 2 * D + h * DK;

    extern __shared__ char smem[];
    const uint32_t sb = smem_u32(smem);
    float* fsm = (float*)smem;
    const int tid = threadIdx.x, wid = tid >> 5, lane = tid & 31;
    const int warp_m = wid & 3;
    const int warp_n = wid >> 2;

    float acc[2][4][4];
#pragma unroll
    for (int a = 0; a < 2; a++)
#pragma unroll
        for (int b = 0; b < 4; b++)
#pragma unroll
            for (int c = 0; c < 4; c++) acc[a][b][c] = 0.0f;

    auto load_stage = [&](int ci, uint32_t st) {
        const int k0 = ci << 5;
        load_tf<128, 256>(A, SQ, brow, k0, st + AV_A, tid);
#pragma unroll
        for (int it = 0; it < 2; it++) {
            int c = tid + (it << 8);
            int r = c >> 4, g = c & 15;
            cpa16(st + AV_B + (uint32_t)(r * 288 + g * 16),
                  V + (size_t)(k0 + r) * (3 * D) + g * 4);
        }
        CPA_COMMIT();
    };

    const int nch = (brow >> 5) + 4;
    load_stage(0, sb);

    const int tileA = lane >> 3;
    const int rinA  = (lane & 7) + ((tileA & 1) << 3);
    const int gA    = tileA >> 1;
    const int g4 = lane >> 2, t4 = lane & 3;

    for (int i = 0; i < nch; i++) {
        if (i + 1 < nch) {
            load_stage(i + 1, sb + ((i + 1) & 1) * AV_SSZ);
            asm volatile("cp.async.wait_group 1;" ::: "memory");
        } else {
            asm volatile("cp.async.wait_group 0;" ::: "memory");
        }
        __syncthreads();

        const uint32_t st = sb + (i & 1) * AV_SSZ;
        const float* vs = fsm + ((i & 1) * AV_SSZ + AV_B) / 4;
#pragma unroll
        for (int ks = 0; ks < 4; ks++) {
            uint32_t b0[4], b1[4];
#pragma unroll
            for (int nt = 0; nt < 4; nt++) {
                const int nn = warp_n * 32 + nt * 8 + g4;
                const int kk = ks * 8 + t4;
                b0[nt] = __float_as_uint(vs[kk * 72 + nn]);
                b1[nt] = __float_as_uint(vs[(kk + 4) * 72 + nn]);
            }
#pragma unroll
            for (int mt = 0; mt < 2; mt++) {
                const int rowa = warp_m * 32 + mt * 16 + rinA;
                uint32_t a0, a1, a2, a3;
                ldm_x4(a0, a1, a2, a3, st + AV_A + swzf(rowa, 2 * ks + gA));
                a0 = f2tf(a0); a1 = f2tf(a1); a2 = f2tf(a2); a3 = f2tf(a3);
#pragma unroll
                for (int nt = 0; nt < 4; nt++)
                    mma_tf32(acc[mt][nt], a0, a1, a2, a3, b0[nt], b1[nt]);
            }
        }
        __syncthreads();
    }

#pragma unroll
    for (int mt = 0; mt < 2; mt++) {
#pragma unroll
        for (int half = 0; half < 2; half++) {
            const int row = brow + warp_m * 32 + mt * 16 + g4 + half * 8;
#pragma unroll
            for (int nt = 0; nt < 4; nt++) {
                const int col = h * DK + warp_n * 32 + nt * 8 + t4 * 2;
                float2 f2 = {f2tff(acc[mt][nt][half * 2 + 0]), f2tff(acc[mt][nt][half * 2 + 1])};
                *(float2*)(ctx + (size_t)row * D + col) = f2;
            }
        }
    }
}

// ================= host driver =================
struct Scratch {
    float *nx, *h, *qkv, *ctx, *mha, *p1, *n2, *n2t, *ff1, *attn;
    float *wint, *wqkvt, *wot, *w2t, *wf1t, *wf2t, *bqkv;
};

static Scratch get_scratch() {
    static Scratch s = [] {
        Scratch t;
        void* p;
        cudaGetSymbolAddress(&p, g_nx);    t.nx   = (float*)p;
        cudaGetSymbolAddress(&p, g_h);     t.h    = (float*)p;
        cudaGetSymbolAddress(&p, g_qkv);   t.qkv  = (float*)p;
        cudaGetSymbolAddress(&p, g_ctx);   t.ctx  = (float*)p;
        cudaGetSymbolAddress(&p, g_mha);   t.mha  = (float*)p;
        cudaGetSymbolAddress(&p, g_p1);    t.p1   = (float*)p;
        cudaGetSymbolAddress(&p, g_n2);    t.n2   = (float*)p;
        cudaGetSymbolAddress(&p, g_n2t);   t.n2t  = (float*)p;
        cudaGetSymbolAddress(&p, g_ff1);   t.ff1  = (float*)p;
        cudaGetSymbolAddress(&p, g_attn_scratch); t.attn = (float*)p;
        cudaGetSymbolAddress(&p, g_wint);  t.wint  = (float*)p;
        cudaGetSymbolAddress(&p, g_wqkvt); t.wqkvt = (float*)p;
        cudaGetSymbolAddress(&p, g_wot);   t.wot   = (float*)p;
        cudaGetSymbolAddress(&p, g_w2t);   t.w2t   = (float*)p;
        cudaGetSymbolAddress(&p, g_wf1t);  t.wf1t  = (float*)p;
        cudaGetSymbolAddress(&p, g_wf2t);  t.wf2t  = (float*)p;
        cudaGetSymbolAddress(&p, g_bqkv);  t.bqkv  = (float*)p;
        cudaFuncSetAttribute((const void*)tf_gemm<64,0,0,1>,  cudaFuncAttributeMaxDynamicSharedMemorySize, GSMEM_64);
        cudaFuncSetAttribute((const void*)tf_gemm<64,0,1,0>,  cudaFuncAttributeMaxDynamicSharedMemorySize, GSMEM_64);
        cudaFuncSetAttribute((const void*)tf_gemm<128,0,0,1>, cudaFuncAttributeMaxDynamicSharedMemorySize, GSMEM_128);
        cudaFuncSetAttribute((const void*)tf_gemm<128,1,0,1>, cudaFuncAttributeMaxDynamicSharedMemorySize, GSMEM_128);
        cudaFuncSetAttribute((const void*)score_mma, cudaFuncAttributeMaxDynamicSharedMemorySize, SCORE_SMEM);
        cudaFuncSetAttribute((const void*)av_mma,    cudaFuncAttributeMaxDynamicSharedMemorySize, AV_SMEM);
        return t;
    }();
    return s;
}

extern "C" void kernel_launch(void* const* d_in, const int* in_sizes, int n_in,
                              void* d_out, int out_size)
{
    const float* x     = (const float*)d_in[0];
    const float* g1    = (const float*)d_in[1];
    const float* beta1 = (const float*)d_in[2];
    const float* W_in  = (const float*)d_in[3];
    const float* b_in  = (const float*)d_in[4];
    const float* Wq    = (const float*)d_in[5];
    const float* bq    = (const float*)d_in[6];
    const float* Wk    = (const float*)d_in[7];
    const float* bk    = (const float*)d_in[8];
    const float* Wv    = (const float*)d_in[9];
    const float* bv    = (const float*)d_in[10];
    const float* Wo    = (const float*)d_in[11];
    const float* bo    = (const float*)d_in[12];
    const float* W2    = (const float*)d_in[13];
    const float* b2    = (const float*)d_in[14];
    const float* g2    = (const float*)d_in[15];
    const float* beta2 = (const float*)d_in[16];
    const float* Wf1   = (const float*)d_in[17];
    const float* bf1   = (const float*)d_in[18];
    const float* Wf2   = (const float*)d_in[19];
    const float* bf2   = (const float*)d_in[20];

    Scratch s = get_scratch();

    float* out  = (float*)d_out;
    const long long full = (long long)SQ * D + (long long)NH * SQ * SQ;
    float* attn = ((long long)out_size >= full) ? (out + (size_t)SQ * D) : s.attn;

    dim3 blk(256);
    dim3 wblk(32, 8);

    // #1/#2: weight prep
    wprep_dd<<<dim3(32, 32, 6), wblk>>>(
        W_in, Wq, Wk, Wv, Wo, W2, bq, bk, bv,
        s.wint, s.wqkvt, s.wot, s.w2t, s.bqkv);
    wprep_ff<<<dim3(128, 32, 2), wblk>>>(Wf1, Wf2, s.wf1t, s.wf2t);

    // #3: LN1 -> tf32
    ln_kernel<0><<<SQ, blk>>>(x, g1, beta1, nullptr, s.nx);
    // #4: h = nx @ W_in + b_in (BN=64: 128 thr, occ 4)
    tf_gemm<64,0,0,1><<<dim3(D/64, SQ/128), 128, GSMEM_64>>>(
        s.nx, s.wint, b_in, nullptr, s.h, D, D);
    // #5: qkv packed (BN=128: 256 thr, warp 32x64)
    tf_gemm<128,0,0,1><<<dim3(3*D/128, SQ/128), 256, GSMEM_128>>>(
        s.h, s.wqkvt, s.bqkv, nullptr, s.qkv, 3*D, D);
    // #6: scores  [ncu -s 5 captures this]
    score_mma<<<dim3(SQ/128, SQ/128, NH), 256, SCORE_SMEM>>>(
        s.qkv, s.qkv + D, attn);
    // #7: softmax
    softmax_kernel<<<dim3(SQ, NH), blk>>>(attn);
    // #8: AV
    av_mma<<<dim3(SQ/128, NH), 256, AV_SMEM>>>(attn, s.qkv, s.ctx);
    // #9: mha = ctx @ Wo + bo
    tf_gemm<64,0,0,1><<<dim3(D/64, SQ/128), 128, GSMEM_64>>>(
        s.ctx, s.wot, bo, nullptr, s.mha, D, D);
    // #10: p1 = x + mha @ W2 + b2
    tf_gemm<64,0,1,0><<<dim3(D/64, SQ/128), 128, GSMEM_64>>>(
        s.mha, s.w2t, b2, x, s.p1, D, D);
    // #11: LN2
    ln_kernel<1><<<SQ, blk>>>(s.p1, g2, beta2, s.n2, s.n2t);
    // #12: ff1 = relu(n2t @ Wf1 + bf1)
    tf_gemm<128,1,0,1><<<dim3(DFF/128, SQ/128), 256, GSMEM_128>>>(
        s.n2t, s.wf1t, bf1, nullptr, s.ff1, DFF, D);
    // #13: out = n2 + ff1 @ Wf2 + bf2 (K=4096)
    tf_gemm<64,0,1,0><<<dim3(D/64, SQ/128), 128, GSMEM_64>>>(
        s.ff1, s.wf2t, bf2, s.n2, out, D, DFF);
}

// round 17
// speedup vs baseline: 1.0441x; 1.0441x over previous
#include <cuda_runtime.h>
#include <cuda_bf16.h>
#include <math.h>
#include <stdint.h>

#define SQ   2048
#define D    1024
#define NH   16
#define DK   64
#define DFF  4096

// ================= PTX helpers (baseline ISA, sm_80-level) ===================
__device__ __forceinline__ uint32_t smem_u32(const void* p) {
    uint32_t a;
    asm("{ .reg .u64 t; cvta.to.shared.u64 t, %1; cvt.u32.u64 %0, t; }" : "=r"(a) : "l"(p));
    return a;
}
__device__ __forceinline__ void cpa16(uint32_t dst, const void* src) {
    asm volatile("cp.async.cg.shared.global [%0], [%1], 16;" :: "r"(dst), "l"(src));
}
#define CPA_COMMIT() asm volatile("cp.async.commit_group;" ::: "memory")
__device__ __forceinline__ void ldm_x4(uint32_t& r0, uint32_t& r1, uint32_t& r2, uint32_t& r3, uint32_t addr) {
    asm volatile("ldmatrix.sync.aligned.m8n8.x4.shared.b16 {%0,%1,%2,%3}, [%4];"
                 : "=r"(r0), "=r"(r1), "=r"(r2), "=r"(r3) : "r"(addr));
}
__device__ __forceinline__ void ldm_x2(uint32_t& r0, uint32_t& r1, uint32_t addr) {
    asm volatile("ldmatrix.sync.aligned.m8n8.x2.shared.b16 {%0,%1}, [%2];"
                 : "=r"(r0), "=r"(r1) : "r"(addr));
}
__device__ __forceinline__ uint32_t f2tf(uint32_t x) {
    uint32_t r;
    asm("cvt.rna.tf32.f32 %0, %1;" : "=r"(r) : "f"(__uint_as_float(x)));
    return r;
}
__device__ __forceinline__ float f2tff(float x) {
    uint32_t r;
    asm("cvt.rna.tf32.f32 %0, %1;" : "=r"(r) : "f"(x));
    return __uint_as_float(r);
}
__device__ __forceinline__ void mma_tf32(float* c, uint32_t a0, uint32_t a1, uint32_t a2, uint32_t a3,
                                         uint32_t b0, uint32_t b1) {
    asm volatile("mma.sync.aligned.m16n8k8.row.col.f32.tf32.tf32.f32 "
                 "{%0,%1,%2,%3}, {%4,%5,%6,%7}, {%8,%9}, {%0,%1,%2,%3};"
                 : "+f"(c[0]), "+f"(c[1]), "+f"(c[2]), "+f"(c[3])
                 : "r"(a0), "r"(a1), "r"(a2), "r"(a3), "r"(b0), "r"(b1));
}
__device__ __forceinline__ float wred_max(float v) {
#pragma unroll
    for (int o = 16; o > 0; o >>= 1) v = fmaxf(v, __shfl_xor_sync(0xffffffffu, v, o));
    return v;
}
__device__ __forceinline__ float wred_sum(float v) {
#pragma unroll
    for (int o = 16; o > 0; o >>= 1) v += __shfl_xor_sync(0xffffffffu, v, o);
    return v;
}

// ================= scratch ====================================================
__device__ float g_nx[SQ * D];
__device__ float g_h[SQ * D];
__device__ float g_qkv[SQ * 3 * D];
__device__ float g_ctx[SQ * D];
__device__ float g_mha[SQ * D];
__device__ float g_p1[SQ * D];
__device__ float g_n2[SQ * D];
__device__ float g_n2t[SQ * D];
__device__ float g_ff1[SQ * DFF];
__device__ float g_attn_scratch[(size_t)NH * SQ * SQ];
__device__ float g_wint[D * D];
__device__ float g_wqkvt[3 * D * D];
__device__ float g_wot[D * D];
__device__ float g_w2t[D * D];
__device__ float g_wf1t[DFF * D];
__device__ float g_wf2t[D * DFF];
__device__ float g_bqkv[3 * D];

// ================= weight prep: transpose + tf32 truncate ====================
__device__ __forceinline__ void wprep_tile(
    const float* __restrict__ W, float* __restrict__ T,
    int K, int N, int rowoff, int n0, int k0)
{
    __shared__ float t[32][33];
    const int tx = threadIdx.x, ty = threadIdx.y;
    for (int i = ty; i < 32; i += 8)
        t[i][tx] = W[(size_t)(k0 + i) * N + n0 + tx];
    __syncthreads();
    for (int i = ty; i < 32; i += 8)
        T[(size_t)(rowoff + n0 + i) * K + k0 + tx] = f2tff(t[tx][i]);
}

__global__ __launch_bounds__(256) void wprep_dd(
    const float* __restrict__ W_in, const float* __restrict__ Wq,
    const float* __restrict__ Wk,   const float* __restrict__ Wv,
    const float* __restrict__ Wo,   const float* __restrict__ W2,
    const float* __restrict__ bq,   const float* __restrict__ bk,
    const float* __restrict__ bv,
    float* wint, float* wqkvt, float* wot, float* w2t, float* bqkv)
{
    const int z = blockIdx.z;
    const float* W; float* T; int rowoff = 0;
    switch (z) {
        case 0:  W = W_in; T = wint;  break;
        case 1:  W = Wq;   T = wqkvt; rowoff = 0;     break;
        case 2:  W = Wk;   T = wqkvt; rowoff = D;     break;
        case 3:  W = Wv;   T = wqkvt; rowoff = 2 * D; break;
        case 4:  W = Wo;   T = wot;   break;
        default: W = W2;   T = w2t;   break;
    }
    wprep_tile(W, T, D, D, rowoff, blockIdx.x * 32, blockIdx.y * 32);
    if (z >= 1 && z <= 3 && blockIdx.x == 0 && blockIdx.y == 0) {
        const float* b = (z == 1) ? bq : (z == 2) ? bk : bv;
        for (int j = threadIdx.y * 32 + threadIdx.x; j < D; j += 256)
            bqkv[(z - 1) * D + j] = b[j];
    }
}

__global__ __launch_bounds__(256) void wprep_ff(
    const float* __restrict__ Wf1, const float* __restrict__ Wf2,
    float* f1t, float* f2t)
{
    if (blockIdx.z == 0)
        wprep_tile(Wf1, f1t, D, DFF, 0, blockIdx.x * 32, blockIdx.y * 32);
    else
        wprep_tile(Wf2, f2t, DFF, D, 0, blockIdx.y * 32, blockIdx.x * 32);
}

// ================= LayerNorm =================================================
template<int DUAL>
__global__ __launch_bounds__(256) void ln_kernel(
    const float* __restrict__ x, const float* __restrict__ g,
    const float* __restrict__ b, float* __restrict__ outf, float* __restrict__ outt)
{
    __shared__ float red[8];
    __shared__ float bc[2];
    const int row = blockIdx.x;
    const int tid = threadIdx.x;
    const int lane = tid & 31, warp = tid >> 5;
    float4 v = *(const float4*)(x + (size_t)row * D + tid * 4);

    float s = wred_sum(v.x + v.y + v.z + v.w);
    if (lane == 0) red[warp] = s;
    __syncthreads();
    if (warp == 0) {
        float t = red[lane & 7];
        t += __shfl_xor_sync(0xffffffffu, t, 1);
        t += __shfl_xor_sync(0xffffffffu, t, 2);
        t += __shfl_xor_sync(0xffffffffu, t, 4);
        if (lane == 0) bc[0] = t;
    }
    __syncthreads();
    const float mean = bc[0] * (1.0f / D);
    const float dx = v.x - mean, dy = v.y - mean, dz = v.z - mean, dw = v.w - mean;

    float s2 = wred_sum(dx * dx + dy * dy + dz * dz + dw * dw);
    if (lane == 0) red[warp] = s2;
    __syncthreads();
    if (warp == 0) {
        float t = red[lane & 7];
        t += __shfl_xor_sync(0xffffffffu, t, 1);
        t += __shfl_xor_sync(0xffffffffu, t, 2);
        t += __shfl_xor_sync(0xffffffffu, t, 4);
        if (lane == 0) bc[1] = t;
    }
    __syncthreads();
    const float inv = 1.0f / (sqrtf(bc[1] * (1.0f / D)) + 1e-6f);

    float4 gg = *(const float4*)(g + tid * 4);
    float4 bb = *(const float4*)(b + tid * 4);
    float o0 = gg.x * dx * inv + bb.x;
    float o1 = gg.y * dy * inv + bb.y;
    float o2 = gg.z * dz * inv + bb.z;
    float o3 = gg.w * dw * inv + bb.w;
    const size_t base = (size_t)row * D + tid * 4;
    if (DUAL) {
        float4 o4 = {o0, o1, o2, o3};
        *(float4*)(outf + base) = o4;
    }
    float4 t4v = {f2tff(o0), f2tff(o1), f2tff(o2), f2tff(o3)};
    *(float4*)(outt + base) = t4v;
}

// ================= shared GEMM plumbing (fp32 tiles, 128B rows) ==============
__device__ __forceinline__ uint32_t swzf(int row, int g) {
    return (uint32_t)(row * 128 + ((g ^ (row & 7)) << 4));
}

template<int ROWS>
__device__ __forceinline__ void load_tf(
    const float* __restrict__ gp, int ld, int row0, int k0, uint32_t sbase, int tid)
{
#pragma unroll
    for (int it = 0; it < ROWS / 32; it++) {
        int c = tid + (it << 8);
        int row = c >> 3, g = c & 7;
        cpa16(sbase + swzf(row, g), gp + (size_t)(row0 + row) * ld + k0 + g * 4);
    }
}

// ================= TF32 GEMM (2-stage, occ 2): C = A[M,K] @ T[N,K]^T =========
// BN=128: BK=32 (stage 32KB). BN=64: BK=64 (two 32-K sub-chunks, stage 48KB,
// halves barrier frequency). Both 256 threads, occ 2.
template<int BN, int RELU, int RESID, int CVT>
__global__ __launch_bounds__(256, 2) void tf_gemm(
    const float* __restrict__ A, const float* __restrict__ B,
    const float* __restrict__ bias, const float* __restrict__ res,
    float* __restrict__ C, int N, int K)
{
    constexpr int MT   = (BN == 128) ? 4 : 2;
    constexpr int NSUB = (BN == 128) ? 1 : 2;       // 32-K sub-chunks per stage
    constexpr int BK   = 32 * NSUB;
    constexpr int ABYT = 16384;                      // one A sub-chunk (128x32 fp32)
    constexpr int BBYT = BN * 128;                   // one B sub-chunk
    constexpr int SBOF = NSUB * ABYT;                // B region offset
    constexpr int SSZ  = NSUB * (ABYT + BBYT);

    extern __shared__ char smem[];
    const uint32_t sb = smem_u32(smem);
    const int tid = threadIdx.x, wid = tid >> 5, lane = tid & 31;
    const int warp_m = (BN == 128) ? (wid & 1) : (wid & 3);
    const int warp_n = (BN == 128) ? (wid >> 1) : (wid >> 2);
    const int brow = blockIdx.y * 128, bcol = blockIdx.x * BN;

    float acc[MT][4][4];
#pragma unroll
    for (int a = 0; a < MT; a++)
#pragma unroll
        for (int b = 0; b < 4; b++)
#pragma unroll
            for (int c = 0; c < 4; c++) acc[a][b][c] = 0.0f;

    const int nch = K / BK;
    auto load_stage = [&](int ci, uint32_t st) {
        const int k0 = ci * BK;
#pragma unroll
        for (int sub = 0; sub < NSUB; sub++) {
            load_tf<128>(A, K, brow, k0 + 32 * sub, st + sub * ABYT, tid);
            load_tf<BN>(B, K, bcol, k0 + 32 * sub, st + SBOF + sub * BBYT, tid);
        }
        CPA_COMMIT();
    };
    load_stage(0, sb);

    const int tileA = lane >> 3;
    const int rinA  = (lane & 7) + ((tileA & 1) << 3);
    const int gA    = tileA >> 1;
    const int i16   = lane & 15;
    const int rinB  = i16 & 7;
    const int gB    = i16 >> 3;

    for (int i = 0; i < nch; i++) {
        if (i + 1 < nch) {
            load_stage(i + 1, sb + ((i + 1) & 1) * SSZ);
            asm volatile("cp.async.wait_group 1;" ::: "memory");
        } else {
            asm volatile("cp.async.wait_group 0;" ::: "memory");
        }
        __syncthreads();

        const uint32_t st = sb + (i & 1) * SSZ;
#pragma unroll
        for (int sub = 0; sub < NSUB; sub++) {
            const uint32_t sA = st + sub * ABYT;
            const uint32_t sB = st + SBOF + sub * BBYT;
#pragma unroll
            for (int ks = 0; ks < 4; ks++) {
                uint32_t b0[4], b1[4];
#pragma unroll
                for (int nt = 0; nt < 4; nt++) {
                    const int rowb = warp_n * 32 + nt * 8 + rinB;
                    ldm_x2(b0[nt], b1[nt], sB + swzf(rowb, 2 * ks + gB));
                }
#pragma unroll
                for (int mt = 0; mt < MT; mt++) {
                    const int rowa = warp_m * (MT * 16) + mt * 16 + rinA;
                    uint32_t a0, a1, a2, a3;
                    ldm_x4(a0, a1, a2, a3, sA + swzf(rowa, 2 * ks + gA));
#pragma unroll
                    for (int nt = 0; nt < 4; nt++)
                        mma_tf32(acc[mt][nt], a0, a1, a2, a3, b0[nt], b1[nt]);
                }
            }
        }
        __syncthreads();
    }

    const int g4 = lane >> 2, t4 = lane & 3;
#pragma unroll
    for (int mt = 0; mt < MT; mt++) {
#pragma unroll
        for (int half = 0; half < 2; half++) {
            const int row = brow + warp_m * (MT * 16) + mt * 16 + g4 + half * 8;
#pragma unroll
            for (int nt = 0; nt < 4; nt++) {
                const int col = bcol + warp_n * 32 + nt * 8 + t4 * 2;
                float v0 = acc[mt][nt][half * 2 + 0] + bias[col];
                float v1 = acc[mt][nt][half * 2 + 1] + bias[col + 1];
                if (RELU) { v0 = fmaxf(v0, 0.0f); v1 = fmaxf(v1, 0.0f); }
                const size_t o = (size_t)row * N + col;
                if (RESID) { v0 += res[o]; v1 += res[o + 1]; }
                if (CVT) { v0 = f2tff(v0); v1 = f2tff(v1); }
                float2 f2 = {v0, v1};
                *(float2*)(C + o) = f2;
            }
        }
    }
}

#define GSMEM_128 (2 * (16384 + 16384))
#define GSMEM_64  (2 * (2 * (16384 + 8192)))

// ================= score (TF32): S = (Q K^T)/8, causal =======================
#define SC_SSZ (16384 + 16384)
#define SCORE_SMEM (2 * SC_SSZ)

__global__ __launch_bounds__(256, 2) void score_mma(
    const float* __restrict__ q, const float* __restrict__ k,
    float* __restrict__ attn)
{
    const int brow = blockIdx.y * 128, bcol = blockIdx.x * 128;
    if (bcol >= brow + 128) return;
    const int h = blockIdx.z;
    const float* A = q + h * DK;
    const float* B = k + h * DK;

    extern __shared__ char smem[];
    const uint32_t sb = smem_u32(smem);
    const int tid = threadIdx.x, wid = tid >> 5, lane = tid & 31;
    const int warp_m = wid & 1, warp_n = wid >> 1;

    float acc[4][4][4];
#pragma unroll
    for (int a = 0; a < 4; a++)
#pragma unroll
        for (int b = 0; b < 4; b++)
#pragma unroll
            for (int c = 0; c < 4; c++) acc[a][b][c] = 0.0f;

    load_tf<128>(A, 3 * D, brow, 0, sb, tid);
    load_tf<128>(B, 3 * D, bcol, 0, sb + 16384, tid);
    CPA_COMMIT();

    const int tileA = lane >> 3;
    const int rinA  = (lane & 7) + ((tileA & 1) << 3);
    const int gA    = tileA >> 1;
    const int i16   = lane & 15;
    const int rinB  = i16 & 7;
    const int gB    = i16 >> 3;

    for (int i = 0; i < 2; i++) {
        if (i == 0) {
            const uint32_t st = sb + SC_SSZ;
            load_tf<128>(A, 3 * D, brow, 32, st, tid);
            load_tf<128>(B, 3 * D, bcol, 32, st + 16384, tid);
            CPA_COMMIT();
            asm volatile("cp.async.wait_group 1;" ::: "memory");
        } else {
            asm volatile("cp.async.wait_group 0;" ::: "memory");
        }
        __syncthreads();

        const uint32_t st = sb + (i & 1) * SC_SSZ;
#pragma unroll
        for (int ks = 0; ks < 4; ks++) {
            uint32_t b0[4], b1[4];
#pragma unroll
            for (int nt = 0; nt < 4; nt++) {
                const int rowb = warp_n * 32 + nt * 8 + rinB;
                ldm_x2(b0[nt], b1[nt], st + 16384 + swzf(rowb, 2 * ks + gB));
            }
#pragma unroll
            for (int mt = 0; mt < 4; mt++) {
                const int rowa = warp_m * 64 + mt * 16 + rinA;
                uint32_t a0, a1, a2, a3;
                ldm_x4(a0, a1, a2, a3, st + swzf(rowa, 2 * ks + gA));
#pragma unroll
                for (int nt = 0; nt < 4; nt++)
                    mma_tf32(acc[mt][nt], a0, a1, a2, a3, b0[nt], b1[nt]);
            }
        }
        __syncthreads();
    }

    const int g4 = lane >> 2, t4 = lane & 3;
#pragma unroll
    for (int mt = 0; mt < 4; mt++) {
#pragma unroll
        for (int half = 0; half < 2; half++) {
            const int row = brow + warp_m * 64 + mt * 16 + g4 + half * 8;
            float* arow = attn + ((size_t)h * SQ + row) * SQ;
#pragma unroll
            for (int nt = 0; nt < 4; nt++) {
                const int col = bcol + warp_n * 32 + nt * 8 + t4 * 2;
                if (col <= row)     arow[col]     = acc[mt][nt][half * 2 + 0] * 0.125f;
                if (col + 1 <= row) arow[col + 1] = acc[mt][nt][half * 2 + 1] * 0.125f;
            }
        }
    }
}

// ================= softmax (fp32, vectorized fills) ==========================
__global__ __launch_bounds__(256) void softmax_kernel(float* __restrict__ attn)
{
    __shared__ float p[SQ];
    __shared__ float red[8];
    __shared__ float bc[2];
    const int i   = blockIdx.x;
    const int h   = blockIdx.y;
    const int tid = threadIdx.x;
    const int lane = tid & 31, warp = tid >> 5;
    float* row = attn + ((size_t)h * SQ + i) * SQ;

    float m = -INFINITY;
    for (int j = tid; j <= i; j += 256) { float s = row[j]; p[j] = s; m = fmaxf(m, s); }
    m = wred_max(m);
    if (lane == 0) red[warp] = m;
    __syncthreads();
    if (warp == 0) {
        float t = red[lane & 7];
        t = fmaxf(t, __shfl_xor_sync(0xffffffffu, t, 1));
        t = fmaxf(t, __shfl_xor_sync(0xffffffffu, t, 2));
        t = fmaxf(t, __shfl_xor_sync(0xffffffffu, t, 4));
        if (lane == 0) bc[0] = t;
    }
    __syncthreads();
    const float mx = bc[0];

    float sum = 0.0f;
    for (int j = tid; j <= i; j += 256) { float e = __expf(p[j] - mx); p[j] = e; sum += e; }
    sum = wred_sum(sum);
    __syncthreads();
    if (lane == 0) red[warp] = sum;
    __syncthreads();
    if (warp == 0) {
        float t = red[lane & 7];
        t += __shfl_xor_sync(0xffffffffu, t, 1);
        t += __shfl_xor_sync(0xffffffffu, t, 2);
        t += __shfl_xor_sync(0xffffffffu, t, 4);
        if (lane == 0) bc[1] = t;
    }
    __syncthreads();
    const float inv = 1.0f / bc[1];

    for (int j = tid; j <= i; j += 256) row[j] = p[j] * inv;

    const int zs = i + 1;
    const int za = (zs + 3) & ~3;
    if (tid < za - zs && zs + tid < SQ) row[zs + tid] = 0.0f;
    const float4 zf4 = {0.0f, 0.0f, 0.0f, 0.0f};
    for (int j = za + tid * 4; j < SQ; j += 1024) *(float4*)(row + j) = zf4;
}

// ================= AV (TF32): ctx = P @ V ====================================
#define AV_A   0
#define AV_B   16384
#define AV_SSZ (16384 + 32 * 72 * 4)
#define AV_SMEM (2 * AV_SSZ)

__global__ __launch_bounds__(256, 2) void av_mma(
    const float* __restrict__ attn, const float* __restrict__ v,
    float* __restrict__ ctx)
{
    const int brow = blockIdx.x * 128;
    const int h    = blockIdx.y;
    const float* A = attn + (size_t)h * SQ * SQ;
    const float* V = v + 2 * D + h * DK;

    extern __shared__ char smem[];
    const uint32_t sb = smem_u32(smem);
    float* fsm = (float*)smem;
    const int tid = threadIdx.x, wid = tid >> 5, lane = tid & 31;
    const int warp_m = wid & 3;
    const int warp_n = wid >> 2;

    float acc[2][4][4];
#pragma unroll
    for (int a = 0; a < 2; a++)
#pragma unroll
        for (int b = 0; b < 4; b++)
#pragma unroll
            for (int c = 0; c < 4; c++) acc[a][b][c] = 0.0f;

    auto load_stage = [&](int ci, uint32_t st) {
        const int k0 = ci << 5;
        load_tf<128>(A, SQ, brow, k0, st + AV_A, tid);
#pragma unroll
        for (int it = 0; it < 2; it++) {
            int c = tid + (it << 8);
            int r = c >> 4, g = c & 15;
            cpa16(st + AV_B + (uint32_t)(r * 288 + g * 16),
                  V + (size_t)(k0 + r) * (3 * D) + g * 4);
        }
        CPA_COMMIT();
    };

    const int nch = (brow >> 5) + 4;
    load_stage(0, sb);

    const int tileA = lane >> 3;
    const int rinA  = (lane & 7) + ((tileA & 1) << 3);
    const int gA    = tileA >> 1;
    const int g4 = lane >> 2, t4 = lane & 3;

    for (int i = 0; i < nch; i++) {
        if (i + 1 < nch) {
            load_stage(i + 1, sb + ((i + 1) & 1) * AV_SSZ);
            asm volatile("cp.async.wait_group 1;" ::: "memory");
        } else {
            asm volatile("cp.async.wait_group 0;" ::: "memory");
        }
        __syncthreads();

        const uint32_t st = sb + (i & 1) * AV_SSZ;
        const float* vs = fsm + ((i & 1) * AV_SSZ + AV_B) / 4;
#pragma unroll
        for (int ks = 0; ks < 4; ks++) {
            uint32_t b0[4], b1[4];
#pragma unroll
            for (int nt = 0; nt < 4; nt++) {
                const int nn = warp_n * 32 + nt * 8 + g4;
                const int kk = ks * 8 + t4;
                b0[nt] = __float_as_uint(vs[kk * 72 + nn]);
                b1[nt] = __float_as_uint(vs[(kk + 4) * 72 + nn]);
            }
#pragma unroll
            for (int mt = 0; mt < 2; mt++) {
                const int rowa = warp_m * 32 + mt * 16 + rinA;
                uint32_t a0, a1, a2, a3;
                ldm_x4(a0, a1, a2, a3, st + AV_A + swzf(rowa, 2 * ks + gA));
                a0 = f2tf(a0); a1 = f2tf(a1); a2 = f2tf(a2); a3 = f2tf(a3);
#pragma unroll
                for (int nt = 0; nt < 4; nt++)
                    mma_tf32(acc[mt][nt], a0, a1, a2, a3, b0[nt], b1[nt]);
            }
        }
        __syncthreads();
    }

#pragma unroll
    for (int mt = 0; mt < 2; mt++) {
#pragma unroll
        for (int half = 0; half < 2; half++) {
            const int row = brow + warp_m * 32 + mt * 16 + g4 + half * 8;
#pragma unroll
            for (int nt = 0; nt < 4; nt++) {
                const int col = h * DK + warp_n * 32 + nt * 8 + t4 * 2;
                float2 f2 = {f2tff(acc[mt][nt][half * 2 + 0]), f2tff(acc[mt][nt][half * 2 + 1])};
                *(float2*)(ctx + (size_t)row * D + col) = f2;
            }
        }
    }
}

// ================= host driver =================
struct Scratch {
    float *nx, *h, *qkv, *ctx, *mha, *p1, *n2, *n2t, *ff1, *attn;
    float *wint, *wqkvt, *wot, *w2t, *wf1t, *wf2t, *bqkv;
};

static Scratch get_scratch() {
    static Scratch s = [] {
        Scratch t;
        void* p;
        cudaGetSymbolAddress(&p, g_nx);    t.nx   = (float*)p;
        cudaGetSymbolAddress(&p, g_h);     t.h    = (float*)p;
        cudaGetSymbolAddress(&p, g_qkv);   t.qkv  = (float*)p;
        cudaGetSymbolAddress(&p, g_ctx);   t.ctx  = (float*)p;
        cudaGetSymbolAddress(&p, g_mha);   t.mha  = (float*)p;
        cudaGetSymbolAddress(&p, g_p1);    t.p1   = (float*)p;
        cudaGetSymbolAddress(&p, g_n2);    t.n2   = (float*)p;
        cudaGetSymbolAddress(&p, g_n2t);   t.n2t  = (float*)p;
        cudaGetSymbolAddress(&p, g_ff1);   t.ff1  = (float*)p;
        cudaGetSymbolAddress(&p, g_attn_scratch); t.attn = (float*)p;
        cudaGetSymbolAddress(&p, g_wint);  t.wint  = (float*)p;
        cudaGetSymbolAddress(&p, g_wqkvt); t.wqkvt = (float*)p;
        cudaGetSymbolAddress(&p, g_wot);   t.wot   = (float*)p;
        cudaGetSymbolAddress(&p, g_w2t);   t.w2t   = (float*)p;
        cudaGetSymbolAddress(&p, g_wf1t);  t.wf1t  = (float*)p;
        cudaGetSymbolAddress(&p, g_wf2t);  t.wf2t  = (float*)p;
        cudaGetSymbolAddress(&p, g_bqkv);  t.bqkv  = (float*)p;
        cudaFuncSetAttribute((const void*)tf_gemm<64,0,0,1>,  cudaFuncAttributeMaxDynamicSharedMemorySize, GSMEM_64);
        cudaFuncSetAttribute((const void*)tf_gemm<64,0,1,0>,  cudaFuncAttributeMaxDynamicSharedMemorySize, GSMEM_64);
        cudaFuncSetAttribute((const void*)tf_gemm<128,0,0,1>, cudaFuncAttributeMaxDynamicSharedMemorySize, GSMEM_128);
        cudaFuncSetAttribute((const void*)tf_gemm<128,1,0,1>, cudaFuncAttributeMaxDynamicSharedMemorySize, GSMEM_128);
        cudaFuncSetAttribute((const void*)score_mma, cudaFuncAttributeMaxDynamicSharedMemorySize, SCORE_SMEM);
        cudaFuncSetAttribute((const void*)av_mma,    cudaFuncAttributeMaxDynamicSharedMemorySize, AV_SMEM);
        return t;
    }();
    return s;
}

extern "C" void kernel_launch(void* const* d_in, const int* in_sizes, int n_in,
                              void* d_out, int out_size)
{
    const float* x     = (const float*)d_in[0];
    const float* g1    = (const float*)d_in[1];
    const float* beta1 = (const float*)d_in[2];
    const float* W_in  = (const float*)d_in[3];
    const float* b_in  = (const float*)d_in[4];
    const float* Wq    = (const float*)d_in[5];
    const float* bq    = (const float*)d_in[6];
    const float* Wk    = (const float*)d_in[7];
    const float* bk    = (const float*)d_in[8];
    const float* Wv    = (const float*)d_in[9];
    const float* bv    = (const float*)d_in[10];
    const float* Wo    = (const float*)d_in[11];
    const float* bo    = (const float*)d_in[12];
    const float* W2    = (const float*)d_in[13];
    const float* b2    = (const float*)d_in[14];
    const float* g2    = (const float*)d_in[15];
    const float* beta2 = (const float*)d_in[16];
    const float* Wf1   = (const float*)d_in[17];
    const float* bf1   = (const float*)d_in[18];
    const float* Wf2   = (const float*)d_in[19];
    const float* bf2   = (const float*)d_in[20];

    Scratch s = get_scratch();

    float* out  = (float*)d_out;
    const long long full = (long long)SQ * D + (long long)NH * SQ * SQ;
    float* attn = ((long long)out_size >= full) ? (out + (size_t)SQ * D) : s.attn;

    dim3 blk(256);
    dim3 wblk(32, 8);

    // #1/#2: weight prep
    wprep_dd<<<dim3(32, 32, 6), wblk>>>(
        W_in, Wq, Wk, Wv, Wo, W2, bq, bk, bv,
        s.wint, s.wqkvt, s.wot, s.w2t, s.bqkv);
    wprep_ff<<<dim3(128, 32, 2), wblk>>>(Wf1, Wf2, s.wf1t, s.wf2t);

    // #3: LN1 -> tf32
    ln_kernel<0><<<SQ, blk>>>(x, g1, beta1, nullptr, s.nx);
    // #4: h = nx @ W_in + b_in (BN=64, BK=64)
    tf_gemm<64,0,0,1><<<dim3(D/64, SQ/128), 256, GSMEM_64>>>(
        s.nx, s.wint, b_in, nullptr, s.h, D, D);
    // #5: qkv packed (BN=128, BK=32)
    tf_gemm<128,0,0,1><<<dim3(3*D/128, SQ/128), 256, GSMEM_128>>>(
        s.h, s.wqkvt, s.bqkv, nullptr, s.qkv, 3*D, D);
    // #6: scores  [ncu -s 5 captures this]
    score_mma<<<dim3(SQ/128, SQ/128, NH), 256, SCORE_SMEM>>>(
        s.qkv, s.qkv + D, attn);
    // #7: softmax
    softmax_kernel<<<dim3(SQ, NH), blk>>>(attn);
    // #8: AV
    av_mma<<<dim3(SQ/128, NH), 256, AV_SMEM>>>(attn, s.qkv, s.ctx);
    // #9: mha = ctx @ Wo + bo (BN=64, BK=64)
    tf_gemm<64,0,0,1><<<dim3(D/64, SQ/128), 256, GSMEM_64>>>(
        s.ctx, s.wot, bo, nullptr, s.mha, D, D);
    // #10: p1 = x + mha @ W2 + b2 (BN=64, BK=64)
    tf_gemm<64,0,1,0><<<dim3(D/64, SQ/128), 256, GSMEM_64>>>(
        s.mha, s.w2t, b2, x, s.p1, D, D);
    // #11: LN2
    ln_kernel<1><<<SQ, blk>>>(s.p1, g2, beta2, s.n2, s.n2t);
    // #12: ff1 = relu(n2t @ Wf1 + bf1) (BN=128, BK=32)
    tf_gemm<128,1,0,1><<<dim3(DFF/128, SQ/128), 256, GSMEM_128>>>(
        s.n2t, s.wf1t, bf1, nullptr, s.ff1, DFF, D);
    // #13: out = n2 + ff1 @ Wf2 + bf2 (BN=64, BK=64, K=4096)
    tf_gemm<64,0,1,0><<<dim3(D/64, SQ/128), 256, GSMEM_64>>>(
        s.ff1, s.wf2t, bf2, s.n2, out, D, DFF);
}